// round 1
// baseline (speedup 1.0000x reference)
#include <cuda_runtime.h>
#include <cuda_bf16.h>

// Problem shape (fixed by the reference): pred [16,4,512,512] f32, target/ME [16,512,512] i32
#define NUM_CLASSES 4
#define IGNORE_INDEX 4
#define BATCH 16
#define HW 262144            // 512*512 (pixels per batch, divisible by 4)
#define NPIX (BATCH * HW)    // 4,194,304
#define NVEC (NPIX / 4)      // 1,048,576 float4-groups

__device__ double g_sum;
__device__ double g_cnt;

__global__ void ce_init_kernel() {
    g_sum = 0.0;
    g_cnt = 0.0;
}

__device__ __forceinline__ void pixel_nll(float v0, float v1, float v2, float v3,
                                          int t, int me,
                                          float& acc, int& cnt) {
    // stable log-sum-exp over the 4 classes
    float m = fmaxf(fmaxf(v0, v1), fmaxf(v2, v3));
    float s = __expf(v0 - m) + __expf(v1 - m) + __expf(v2 - m) + __expf(v3 - m);
    float lse = m + __logf(s);
    // gather target class value (t==4 handled by mask; clip keeps it valid)
    int tc = min(t, NUM_CLASSES - 1);
    float vt = (tc == 0) ? v0 : (tc == 1) ? v1 : (tc == 2) ? v2 : v3;
    float nll = lse - vt;
    float w = (me == 0) ? 1.0f : 0.5f;
    bool valid = (t != IGNORE_INDEX);
    acc += valid ? (w * nll) : 0.0f;
    cnt += valid ? 1 : 0;
}

__global__ void __launch_bounds__(256)
ce_main_kernel(const float* __restrict__ pred,
               const int* __restrict__ target,
               const int* __restrict__ me) {
    float acc = 0.0f;
    int cnt = 0;

    const int stride = gridDim.x * blockDim.x;
    for (int i = blockIdx.x * blockDim.x + threadIdx.x; i < NVEC; i += stride) {
        int p = i << 2;              // first pixel of this group
        int b = p / HW;
        int hw = p - b * HW;
        size_t base = (size_t)b * NUM_CLASSES * HW + hw;

        float4 c0 = *reinterpret_cast<const float4*>(pred + base);
        float4 c1 = *reinterpret_cast<const float4*>(pred + base + HW);
        float4 c2 = *reinterpret_cast<const float4*>(pred + base + 2 * (size_t)HW);
        float4 c3 = *reinterpret_cast<const float4*>(pred + base + 3 * (size_t)HW);
        int4 tg = *reinterpret_cast<const int4*>(target + p);
        int4 mv = *reinterpret_cast<const int4*>(me + p);

        pixel_nll(c0.x, c1.x, c2.x, c3.x, tg.x, mv.x, acc, cnt);
        pixel_nll(c0.y, c1.y, c2.y, c3.y, tg.y, mv.y, acc, cnt);
        pixel_nll(c0.z, c1.z, c2.z, c3.z, tg.z, mv.z, acc, cnt);
        pixel_nll(c0.w, c1.w, c2.w, c3.w, tg.w, mv.w, acc, cnt);
    }

    // warp reduction
    float fc = (float)cnt;
    #pragma unroll
    for (int off = 16; off > 0; off >>= 1) {
        acc += __shfl_down_sync(0xFFFFFFFFu, acc, off);
        fc  += __shfl_down_sync(0xFFFFFFFFu, fc,  off);
    }

    // block reduction across 8 warps
    __shared__ float s_acc[8];
    __shared__ float s_cnt[8];
    int wid = threadIdx.x >> 5;
    int lid = threadIdx.x & 31;
    if (lid == 0) { s_acc[wid] = acc; s_cnt[wid] = fc; }
    __syncthreads();
    if (wid == 0) {
        float a = (lid < 8) ? s_acc[lid] : 0.0f;
        float c = (lid < 8) ? s_cnt[lid] : 0.0f;
        #pragma unroll
        for (int off = 4; off > 0; off >>= 1) {
            a += __shfl_down_sync(0xFFFFFFFFu, a, off);
            c += __shfl_down_sync(0xFFFFFFFFu, c, off);
        }
        if (lid == 0) {
            atomicAdd(&g_sum, (double)a);
            atomicAdd(&g_cnt, (double)c);
        }
    }
}

__global__ void ce_final_kernel(float* out) {
    out[0] = (float)(g_sum / g_cnt);
}

extern "C" void kernel_launch(void* const* d_in, const int* in_sizes, int n_in,
                              void* d_out, int out_size) {
    const float* pred   = (const float*)d_in[0];
    const int*   target = (const int*)d_in[1];
    const int*   me     = (const int*)d_in[2];
    float* out = (float*)d_out;

    ce_init_kernel<<<1, 1>>>();
    ce_main_kernel<<<2048, 256>>>(pred, target, me);
    ce_final_kernel<<<1, 1>>>(out);
}